// round 5
// baseline (speedup 1.0000x reference)
#include <cuda_runtime.h>

// ---------------------------------------------------------------------------
// PolicyGradientLoss: out = mean( nll(w, a) * (D - mean(D)) )
//   D[t] = sum_{k>=t} gamma^{k-t} * r[k]   (reverse affine scan)
//   nll[t] = logsumexp(w[t,:]) - w[t, a[t]]
// Identity: mean(nll*(D-mD)) = (S_pd - S_d*S_n/T)/T
// NOTE: ep_as is int32 on device (JAX x64 disabled downgrades int64->int32).
// ---------------------------------------------------------------------------

#define GAMMA 0.99f
#define THREADS 256
#define PT 16                      // elements per thread in scan kernels
#define CHUNK (THREADS * PT)       // 4096 elements per chunk/block
#define MAXT (1 << 22)
#define MAXC (MAXT / CHUNK)        // 1024

static __device__ float  g_d[MAXT];     // discounted returns scratch
static __device__ float  g_cg[MAXC];    // per-chunk gamma^len
static __device__ float  g_cs[MAXC];    // per-chunk local sum
static __device__ float  g_cin[MAXC];   // carry entering each chunk from right
static __device__ double g_acc[3];      // [0]=sum d, [1]=sum nll, [2]=sum nll*d

__device__ __forceinline__ float gamma_pt() {
    float g2 = GAMMA * GAMMA;
    float g4 = g2 * g2;
    float g8 = g4 * g4;
    return g8 * g8; // gamma^16 (PT==16)
}

// Load PT consecutive floats (zero-padded past T)
__device__ __forceinline__ void load_pt(const float* __restrict__ r, long long base,
                                        long long T, float rv[PT]) {
    if (base + PT <= T) {
        const float4* p = reinterpret_cast<const float4*>(r + base);
        float4 v0 = p[0], v1 = p[1], v2 = p[2], v3 = p[3];
        rv[0]=v0.x; rv[1]=v0.y; rv[2]=v0.z; rv[3]=v0.w;
        rv[4]=v1.x; rv[5]=v1.y; rv[6]=v1.z; rv[7]=v1.w;
        rv[8]=v2.x; rv[9]=v2.y; rv[10]=v2.z; rv[11]=v2.w;
        rv[12]=v3.x; rv[13]=v3.y; rv[14]=v3.z; rv[15]=v3.w;
    } else {
        #pragma unroll
        for (int j = 0; j < PT; j++)
            rv[j] = (base + j < T) ? r[base + j] : 0.0f;
    }
}

// Inclusive suffix scan over shared (g,s) pairs: after this, (sg[i],ss[i]) is
// the aggregate of segments [i..THREADS-1]. combine(L,R) = (gL*gR, sL + gL*sR).
__device__ __forceinline__ void suffix_scan(float* sg, float* ss) {
    int tid = threadIdx.x;
    #pragma unroll
    for (int off = 1; off < THREADS; off <<= 1) {
        float gn = 1.0f, sn = 0.0f;
        if (tid + off < THREADS) { gn = sg[tid + off]; sn = ss[tid + off]; }
        float go = sg[tid], so = ss[tid];
        __syncthreads();
        sg[tid] = go * gn;
        ss[tid] = so + go * sn;
        __syncthreads();
    }
}

// Two-value double block reduction + atomics
__device__ __forceinline__ void block_reduce2_atomic(double a, double b,
                                                     double* dsta, double* dstb) {
    #pragma unroll
    for (int o = 16; o > 0; o >>= 1) {
        a += __shfl_down_sync(0xffffffffu, a, o);
        b += __shfl_down_sync(0xffffffffu, b, o);
    }
    __shared__ double sa[8], sb[8];
    int lane = threadIdx.x & 31, wid = threadIdx.x >> 5;
    if (lane == 0) { sa[wid] = a; sb[wid] = b; }
    __syncthreads();
    if (wid == 0) {
        int nw = blockDim.x >> 5;
        a = (lane < nw) ? sa[lane] : 0.0;
        b = (lane < nw) ? sb[lane] : 0.0;
        #pragma unroll
        for (int o = 4; o > 0; o >>= 1) {
            a += __shfl_down_sync(0xffffffffu, a, o);
            b += __shfl_down_sync(0xffffffffu, b, o);
        }
        if (lane == 0) { atomicAdd(dsta, a); atomicAdd(dstb, b); }
    }
}

__global__ void k_zero() {
    g_acc[0] = 0.0; g_acc[1] = 0.0; g_acc[2] = 0.0;
}

// Phase 1: per-chunk aggregates (g = gamma^CHUNK, s = local reverse-scan head)
__global__ void k_scan1(const float* __restrict__ r, long long T) {
    __shared__ float sg[THREADS], ss[THREADS];
    int tid = threadIdx.x;
    int c = blockIdx.x;
    long long base = (long long)c * CHUNK + (long long)tid * PT;
    float rv[PT];
    load_pt(r, base, T, rv);
    float carry = 0.0f;
    #pragma unroll
    for (int j = PT - 1; j >= 0; --j) carry = carry * GAMMA + rv[j];
    sg[tid] = gamma_pt();
    ss[tid] = carry;
    __syncthreads();
    suffix_scan(sg, ss);
    if (tid == 0) { g_cg[c] = sg[0]; g_cs[c] = ss[0]; }
}

// Phase 2: single-block suffix scan over chunk aggregates -> carry into each chunk
__global__ void k_scan2(int nchunk) {
    __shared__ float sg[THREADS], ss[THREADS];
    int tid = threadIdx.x;
    int kc = (nchunk + THREADS - 1) / THREADS;
    int lo = tid * kc;
    int hi = min(lo + kc, nchunk);
    float g = 1.0f, s = 0.0f;
    for (int c = lo; c < hi; c++) {   // append chunk c on the right
        s = s + g * g_cs[c];
        g = g * g_cg[c];
    }
    sg[tid] = g; ss[tid] = s;
    __syncthreads();
    suffix_scan(sg, ss);
    float es = 0.0f;
    if (tid + 1 < THREADS) { es = ss[tid + 1]; }
    float carry = es;                 // suffix applied to terminal carry 0
    for (int c = hi - 1; c >= lo; --c) {
        g_cin[c] = carry;
        carry = g_cs[c] + g_cg[c] * carry;
    }
}

// Phase 3: replay each chunk with its incoming carry, write d[], accumulate sum(d)
__global__ void k_scan3(const float* __restrict__ r, long long T) {
    __shared__ float sg[THREADS], ss[THREADS];
    int tid = threadIdx.x;
    int c = blockIdx.x;
    long long base = (long long)c * CHUNK + (long long)tid * PT;
    float rv[PT];
    load_pt(r, base, T, rv);
    float carry = 0.0f;
    #pragma unroll
    for (int j = PT - 1; j >= 0; --j) carry = carry * GAMMA + rv[j];
    sg[tid] = gamma_pt();
    ss[tid] = carry;
    __syncthreads();
    suffix_scan(sg, ss);
    float eg = 1.0f, es = 0.0f;
    if (tid + 1 < THREADS) { eg = sg[tid + 1]; es = ss[tid + 1]; }
    float cin = g_cin[c];
    float tc = es + eg * cin;         // carry entering this thread's segment

    float dloc[PT];
    carry = tc;
    #pragma unroll
    for (int j = PT - 1; j >= 0; --j) {
        carry = carry * GAMMA + rv[j];
        dloc[j] = carry;
    }

    double dsum = 0.0;
    if (base + PT <= T) {
        float4* out = reinterpret_cast<float4*>(g_d + base);
        out[0] = make_float4(dloc[0], dloc[1], dloc[2], dloc[3]);
        out[1] = make_float4(dloc[4], dloc[5], dloc[6], dloc[7]);
        out[2] = make_float4(dloc[8], dloc[9], dloc[10], dloc[11]);
        out[3] = make_float4(dloc[12], dloc[13], dloc[14], dloc[15]);
        #pragma unroll
        for (int j = 0; j < PT; j++) dsum += (double)dloc[j];
    } else {
        #pragma unroll
        for (int j = 0; j < PT; j++)
            if (base + j < T) { g_d[base + j] = dloc[j]; dsum += (double)dloc[j]; }
    }
    __syncthreads(); // scan shared arrays no longer needed
    double dummy = 0.0;
    block_reduce2_atomic(dsum, dummy, &g_acc[0], &g_acc[1]); // adds 0 to acc[1]
}

// Main loss pass: nll per row + accumulate sum(nll), sum(nll*d)
template <int A>
__global__ void k_loss(const float* __restrict__ w,
                       const int* __restrict__ as, long long T) {
    double pn = 0.0, pp = 0.0;
    long long stride = (long long)gridDim.x * blockDim.x;
    for (long long t = (long long)blockIdx.x * blockDim.x + threadIdx.x;
         t < T; t += stride) {
        const float* row = w + (size_t)t * A;
        float x[A];
        const float2* p2 = reinterpret_cast<const float2*>(row); // 8B aligned (A even)
        #pragma unroll
        for (int i = 0; i < A / 2; i++) {
            float2 v = __ldg(p2 + i);
            x[2 * i] = v.x; x[2 * i + 1] = v.y;
        }
        float s = 0.0f;
        #pragma unroll
        for (int i = 0; i < A; i++) s += __expf(x[i]);
        int ai = as[t];
        float wa = __ldg(row + ai);                 // L1 hit (avoids reg-indexed array)
        float nll = __logf(s) - wa;
        float d = g_d[t];
        pn += (double)nll;
        pp += (double)(nll * d);
    }
    block_reduce2_atomic(pn, pp, &g_acc[1], &g_acc[2]);
}

__global__ void k_loss_gen(const float* __restrict__ w,
                           const int* __restrict__ as,
                           long long T, int A) {
    double pn = 0.0, pp = 0.0;
    long long stride = (long long)gridDim.x * blockDim.x;
    for (long long t = (long long)blockIdx.x * blockDim.x + threadIdx.x;
         t < T; t += stride) {
        const float* row = w + (size_t)t * A;
        float m = __ldg(row);
        for (int i = 1; i < A; i++) m = fmaxf(m, __ldg(row + i));
        float s = 0.0f;
        for (int i = 0; i < A; i++) s += __expf(__ldg(row + i) - m);
        int ai = as[t];
        float nll = m + __logf(s) - __ldg(row + ai);
        float d = g_d[t];
        pn += (double)nll;
        pp += (double)(nll * d);
    }
    block_reduce2_atomic(pn, pp, &g_acc[1], &g_acc[2]);
}

__global__ void k_final(float* out, double Td) {
    double ds = g_acc[0], ns = g_acc[1], ps = g_acc[2];
    out[0] = (float)((ps - ds * ns / Td) / Td);
}

extern "C" void kernel_launch(void* const* d_in, const int* in_sizes, int n_in,
                              void* d_out, int out_size) {
    const float* w  = (const float*)d_in[0];   // [T, A]
    const float* r  = (const float*)d_in[1];   // [T]
    const int*   as = (const int*)d_in[2];     // [T] (int32 on device!)
    long long T = (long long)in_sizes[1];
    int A = (int)((long long)in_sizes[0] / T);
    int NC = (int)((T + CHUNK - 1) / CHUNK);
    if (NC > MAXC) NC = MAXC; // safety clamp (benchmark shape fits)

    k_zero<<<1, 1>>>();
    k_scan1<<<NC, THREADS>>>(r, T);
    k_scan2<<<1, THREADS>>>(NC);
    k_scan3<<<NC, THREADS>>>(r, T);

    int blocks = 1184; // 148 SMs * 8
    long long need = (T + 255) / 256;
    if ((long long)blocks > need) blocks = (int)need;
    if (blocks < 1) blocks = 1;
    if (A == 18) k_loss<18><<<blocks, 256>>>(w, as, T);
    else         k_loss_gen<<<blocks, 256>>>(w, as, T, A);

    k_final<<<1, 1>>>((float*)d_out, (double)T);
}

// round 6
// speedup vs baseline: 1.2319x; 1.2319x over previous
#include <cuda_runtime.h>
#include <math.h>

// ---------------------------------------------------------------------------
// PolicyGradientLoss: out = mean( nll(w,a) * (D - mean D) )
//   D[t] = sum_{k>=t} gamma^{k-t} r[k]
//   nll[t] = logsumexp(w[t,:]) - w[t, a[t]]
// Identity: mean(nll*(D-mD)) = (S_pd - S_d*S_n/T)/T
// ep_as is int32 on device (JAX x64 disabled).
//
// Structure (R6): fused scan-replay + loss. No g_d array.
//   k_agg   : per-chunk (g, s) aggregates of the reverse affine scan over r
//   k_scan2 : suffix scan over chunk aggregates -> carry into each chunk
//   k_fused : rebuild d for the chunk in smem, fused logsumexp loss, 3 sums
//   k_final : combine
// ---------------------------------------------------------------------------

#define GAMMA 0.99f
#define BT 256                         // threads per block
#define FPT 8                          // rows per thread (scan segment)
#define FCHUNK (BT * FPT)              // 2048 rows per block
#define MAXT (1 << 22)
#define MAXC (MAXT / FCHUNK)           // 2048

static __device__ float  g_cg[MAXC];
static __device__ float  g_cs[MAXC];
static __device__ float  g_cin[MAXC];
static __device__ double g_acc[3];     // [0]=sum d, [1]=sum nll, [2]=sum nll*d

__device__ __forceinline__ float gamma8() {
    float g2 = GAMMA * GAMMA; float g4 = g2 * g2; return g4 * g4;
}

// Load FPT consecutive floats, zero-padded past T. base is FPT-aligned.
__device__ __forceinline__ void load8(const float* __restrict__ r, long long base,
                                      long long T, float rv[FPT]) {
    if (base + FPT <= T) {
        const float4* p = reinterpret_cast<const float4*>(r + base);
        float4 v0 = p[0], v1 = p[1];
        rv[0]=v0.x; rv[1]=v0.y; rv[2]=v0.z; rv[3]=v0.w;
        rv[4]=v1.x; rv[5]=v1.y; rv[6]=v1.z; rv[7]=v1.w;
    } else {
        #pragma unroll
        for (int j = 0; j < FPT; j++)
            rv[j] = (base + j < T) ? r[base + j] : 0.0f;
    }
}

// Warp-level inclusive suffix scan of (g,s): lane i gets aggregate [i..31].
// combine(L,R): s = sL + gL*sR ; g = gL*gR
__device__ __forceinline__ void warp_suffix_incl(float& g, float& s) {
    int lane = threadIdx.x & 31;
    #pragma unroll
    for (int off = 1; off < 32; off <<= 1) {
        float g2 = __shfl_down_sync(0xffffffffu, g, off);
        float s2 = __shfl_down_sync(0xffffffffu, s, off);
        if (lane + off < 32) { s = s + g * s2; g = g * g2; }
    }
}

// Given this thread's segment aggregate (gseg, sseg) and the carry VALUE
// entering the block from the right (cin), return the carry value entering
// this thread's segment. shg/shs: shared scratch [nwarps]. Leaves shg/shs
// holding warp aggregates (tid 0 can form the block aggregate afterwards).
__device__ __forceinline__ float thread_carry(float gseg, float sseg, float cin,
                                              float* shg, float* shs) {
    int lane = threadIdx.x & 31, wid = threadIdx.x >> 5;
    int nw = blockDim.x >> 5;
    float g = gseg, s = sseg;
    warp_suffix_incl(g, s);
    // exclusive-from-right within warp
    float ge = __shfl_down_sync(0xffffffffu, g, 1);
    float se = __shfl_down_sync(0xffffffffu, s, 1);
    if (lane == 31) { ge = 1.0f; se = 0.0f; }
    if (lane == 0) { shg[wid] = g; shs[wid] = s; }   // warp aggregate
    __syncthreads();
    // aggregate of warps [wid+1 .. nw-1], left-to-right composition
    float gw = 1.0f, sw = 0.0f;
    for (int wv = wid + 1; wv < nw; wv++) { sw = sw + gw * shs[wv]; gw = gw * shg[wv]; }
    return se + ge * (sw + gw * cin);
}

// Three-value double block reduction + atomics to g_acc
__device__ __forceinline__ void block_reduce3(double a, double b, double c) {
    #pragma unroll
    for (int o = 16; o > 0; o >>= 1) {
        a += __shfl_down_sync(0xffffffffu, a, o);
        b += __shfl_down_sync(0xffffffffu, b, o);
        c += __shfl_down_sync(0xffffffffu, c, o);
    }
    __shared__ double sa[8], sb[8], sc[8];
    int lane = threadIdx.x & 31, wid = threadIdx.x >> 5;
    if (lane == 0) { sa[wid] = a; sb[wid] = b; sc[wid] = c; }
    __syncthreads();
    if (wid == 0) {
        int nw = blockDim.x >> 5;
        a = (lane < nw) ? sa[lane] : 0.0;
        b = (lane < nw) ? sb[lane] : 0.0;
        c = (lane < nw) ? sc[lane] : 0.0;
        #pragma unroll
        for (int o = 4; o > 0; o >>= 1) {
            a += __shfl_down_sync(0xffffffffu, a, o);
            b += __shfl_down_sync(0xffffffffu, b, o);
            c += __shfl_down_sync(0xffffffffu, c, o);
        }
        if (lane == 0) {
            atomicAdd(&g_acc[0], a);
            atomicAdd(&g_acc[1], b);
            atomicAdd(&g_acc[2], c);
        }
    }
}

__global__ void k_zero() { g_acc[0] = 0.0; g_acc[1] = 0.0; g_acc[2] = 0.0; }

// Phase 1: per-chunk aggregates
__global__ void __launch_bounds__(BT) k_agg(const float* __restrict__ r, long long T) {
    __shared__ float shg[BT / 32], shs[BT / 32];
    int tid = threadIdx.x;
    long long base = (long long)blockIdx.x * FCHUNK + (long long)tid * FPT;
    float rv[FPT];
    load8(r, base, T, rv);
    int cnt = (int)max(0LL, min((long long)FPT, T - base));
    float carry = 0.0f;
    #pragma unroll
    for (int j = FPT - 1; j >= 0; --j) carry = carry * GAMMA + rv[j];  // zeros pad s correctly
    float gseg = (cnt == FPT) ? gamma8() : __powf(GAMMA, (float)cnt);
    // warp scans fill shg/shs with warp aggregates (thread_carry does the work)
    (void)thread_carry(gseg, carry, 0.0f, shg, shs);
    __syncthreads();
    if (tid == 0) {
        int nw = blockDim.x >> 5;
        float g = 1.0f, s = 0.0f;
        for (int wv = 0; wv < nw; wv++) { s = s + g * shs[wv]; g = g * shg[wv]; }
        g_cg[blockIdx.x] = g; g_cs[blockIdx.x] = s;
    }
}

// Phase 2: suffix scan over chunk aggregates -> carry value entering each chunk
__global__ void __launch_bounds__(BT) k_scan2(int nchunk) {
    __shared__ float shg[BT / 32], shs[BT / 32];
    int tid = threadIdx.x;
    int kc = (nchunk + BT - 1) / BT;
    int lo = tid * kc;
    int hi = min(lo + kc, nchunk);
    float g = 1.0f, s = 0.0f;
    for (int c = lo; c < hi; c++) { s = s + g * g_cs[c]; g = g * g_cg[c]; }
    float carry = thread_carry(g, s, 0.0f, shg, shs);  // carry entering [lo..hi)
    for (int c = hi - 1; c >= lo; --c) {
        g_cin[c] = carry;
        carry = g_cs[c] + g_cg[c] * carry;
    }
}

// Phase 3 (fused): rebuild d for this chunk in smem, then loss pass.
template <int A>
__global__ void __launch_bounds__(BT) k_fused(const float* __restrict__ w,
                                              const float* __restrict__ r,
                                              const int* __restrict__ as,
                                              long long T) {
    __shared__ float sd[FCHUNK];
    __shared__ float shg[BT / 32], shs[BT / 32];
    int tid = threadIdx.x;
    long long cbase = (long long)blockIdx.x * FCHUNK;
    long long base = cbase + (long long)tid * FPT;

    // --- scan replay ---
    float rv[FPT];
    load8(r, base, T, rv);
    int cnt = (int)max(0LL, min((long long)FPT, T - base));
    float carry = 0.0f;
    #pragma unroll
    for (int j = FPT - 1; j >= 0; --j) carry = carry * GAMMA + rv[j];
    float gseg = (cnt == FPT) ? gamma8() : __powf(GAMMA, (float)cnt);
    float cin = g_cin[blockIdx.x];
    float tc = thread_carry(gseg, carry, cin, shg, shs);

    double dsum = 0.0;
    {
        float c2 = tc;
        float dloc[FPT];
        if (cnt == FPT) {
            #pragma unroll
            for (int j = FPT - 1; j >= 0; --j) { c2 = c2 * GAMMA + rv[j]; dloc[j] = c2; }
            #pragma unroll
            for (int j = 0; j < FPT; j++) { sd[tid * FPT + j] = dloc[j]; dsum += (double)dloc[j]; }
        } else {
            for (int j = FPT - 1; j >= 0; --j) {
                if (j < cnt) { c2 = c2 * GAMMA + rv[j]; sd[tid * FPT + j] = c2; dsum += (double)c2; }
                else sd[tid * FPT + j] = 0.0f;
            }
        }
    }
    __syncthreads();

    // --- loss pass (coalesced block-stride over this chunk) ---
    double pn = 0.0, pp = 0.0;
    #pragma unroll
    for (int j = 0; j < FPT; j++) {
        long long t = cbase + (long long)j * BT + tid;
        if (t < T) {
            const float* row = w + (size_t)t * A;
            float x[A];
            const float2* p2 = reinterpret_cast<const float2*>(row);
            #pragma unroll
            for (int i = 0; i < A / 2; i++) {
                float2 v = __ldg(p2 + i);
                x[2 * i] = v.x; x[2 * i + 1] = v.y;
            }
            if (A & 1) x[A - 1] = __ldg(row + A - 1);
            float s = 0.0f;
            #pragma unroll
            for (int i = 0; i < A; i++) s += __expf(x[i]);
            int ai = as[t];
            float wa = __ldg(row + ai);               // L1 hit
            float nll = __logf(s) - wa;
            float d = sd[j * BT + tid];
            pn += (double)nll;
            pp += (double)(nll * d);
        }
    }
    block_reduce3(dsum, pn, pp);
}

// Generic-A fallback
__global__ void __launch_bounds__(BT) k_fused_gen(const float* __restrict__ w,
                                                  const float* __restrict__ r,
                                                  const int* __restrict__ as,
                                                  long long T, int A) {
    __shared__ float sd[FCHUNK];
    __shared__ float shg[BT / 32], shs[BT / 32];
    int tid = threadIdx.x;
    long long cbase = (long long)blockIdx.x * FCHUNK;
    long long base = cbase + (long long)tid * FPT;

    float rv[FPT];
    load8(r, base, T, rv);
    int cnt = (int)max(0LL, min((long long)FPT, T - base));
    float carry = 0.0f;
    #pragma unroll
    for (int j = FPT - 1; j >= 0; --j) carry = carry * GAMMA + rv[j];
    float gseg = (cnt == FPT) ? gamma8() : __powf(GAMMA, (float)cnt);
    float tc = thread_carry(gseg, carry, g_cin[blockIdx.x], shg, shs);

    double dsum = 0.0;
    {
        float c2 = tc;
        for (int j = FPT - 1; j >= 0; --j) {
            if (j < cnt) { c2 = c2 * GAMMA + rv[j]; sd[tid * FPT + j] = c2; dsum += (double)c2; }
            else sd[tid * FPT + j] = 0.0f;
        }
    }
    __syncthreads();

    double pn = 0.0, pp = 0.0;
    for (int j = 0; j < FPT; j++) {
        long long t = cbase + (long long)j * BT + tid;
        if (t < T) {
            const float* row = w + (size_t)t * A;
            float m = __ldg(row);
            for (int i = 1; i < A; i++) m = fmaxf(m, __ldg(row + i));
            float s = 0.0f;
            for (int i = 0; i < A; i++) s += __expf(__ldg(row + i) - m);
            int ai = as[t];
            float nll = m + __logf(s) - __ldg(row + ai);
            float d = sd[j * BT + tid];
            pn += (double)nll;
            pp += (double)(nll * d);
        }
    }
    block_reduce3(dsum, pn, pp);
}

__global__ void k_final(float* out, double Td) {
    double ds = g_acc[0], ns = g_acc[1], ps = g_acc[2];
    out[0] = (float)((ps - ds * ns / Td) / Td);
}

extern "C" void kernel_launch(void* const* d_in, const int* in_sizes, int n_in,
                              void* d_out, int out_size) {
    const float* w  = (const float*)d_in[0];   // [T, A]
    const float* r  = (const float*)d_in[1];   // [T]
    const int*   as = (const int*)d_in[2];     // [T] int32
    long long T = (long long)in_sizes[1];
    int A = (int)((long long)in_sizes[0] / T);
    long long NCll = (T + FCHUNK - 1) / FCHUNK;
    if (NCll > MAXC) NCll = MAXC;              // bench shape fits (1024)
    int NC = (int)NCll;

    k_zero<<<1, 1>>>();
    k_agg<<<NC, BT>>>(r, T);
    k_scan2<<<1, BT>>>(NC);
    if (A == 18) k_fused<18><<<NC, BT>>>(w, r, as, T);
    else         k_fused_gen<<<NC, BT>>>(w, r, as, T, A);
    k_final<<<1, 1>>>((float*)d_out, (double)T);
}